// round 9
// baseline (speedup 1.0000x reference)
#include <cuda_runtime.h>
#include <cuda_bf16.h>

// SiLU(x) = x * sigmoid(x), elementwise, n = 134217728 fp32.
// HBM-bound stream at the ~86% mixed R/W ceiling. New axis: Blackwell 256-bit
// vector loads/stores (ld/st.global.cs.v8.f32) — 2 front-batched LDG.256 per
// thread, 512-thread blocks, tile = 8192 floats, grid = 16384, evict-first.

__device__ __forceinline__ float silu1(float x) {
    float s = 1.0f / (1.0f + __expf(-x));
    return x * s;
}

__device__ __forceinline__ float4 silu4(float4 v) {
    float4 r;
    r.x = silu1(v.x);
    r.y = silu1(v.y);
    r.z = silu1(v.z);
    r.w = silu1(v.w);
    return r;
}

__device__ __forceinline__ void ldg256_cs(const float* p, float* v) {
    asm volatile(
        "ld.global.cs.v8.f32 {%0,%1,%2,%3,%4,%5,%6,%7}, [%8];"
        : "=f"(v[0]), "=f"(v[1]), "=f"(v[2]), "=f"(v[3]),
          "=f"(v[4]), "=f"(v[5]), "=f"(v[6]), "=f"(v[7])
        : "l"(p));
}

__device__ __forceinline__ void stg256_cs(float* p, const float* v) {
    asm volatile(
        "st.global.cs.v8.f32 [%0], {%1,%2,%3,%4,%5,%6,%7,%8};"
        :: "l"(p),
           "f"(v[0]), "f"(v[1]), "f"(v[2]), "f"(v[3]),
           "f"(v[4]), "f"(v[5]), "f"(v[6]), "f"(v[7])
        : "memory");
}

// Full-tile kernel: every block owns exactly 8192 floats, no guards.
// Thread t handles 8 floats at base+t*8 and 8 floats at base+t*8+4096.
__global__ void __launch_bounds__(512) silu_v8_full_kernel(
    const float* __restrict__ in, float* __restrict__ out)
{
    unsigned base = blockIdx.x * 8192u + threadIdx.x * 8u;

    float a[8], b[8];
    ldg256_cs(in + base, a);
    ldg256_cs(in + base + 4096, b);

    float ra[8], rb[8];
    #pragma unroll
    for (int k = 0; k < 8; k++) ra[k] = silu1(a[k]);
    #pragma unroll
    for (int k = 0; k < 8; k++) rb[k] = silu1(b[k]);

    stg256_cs(out + base, ra);
    stg256_cs(out + base + 4096, rb);
}

// R6 winner kept as secondary fast path.
__global__ void __launch_bounds__(512) silu_b512_full_kernel(
    const float4* __restrict__ in, float4* __restrict__ out)
{
    unsigned base = blockIdx.x * 2048u + threadIdx.x;
    float4 v0 = __ldcs(in + base);
    float4 v1 = __ldcs(in + base + 512);
    float4 v2 = __ldcs(in + base + 1024);
    float4 v3 = __ldcs(in + base + 1536);
    __stcs(out + base,        silu4(v0));
    __stcs(out + base + 512,  silu4(v1));
    __stcs(out + base + 1024, silu4(v2));
    __stcs(out + base + 1536, silu4(v3));
}

// Generic guarded kernel (fallback for shapes not divisible by tile).
__global__ void __launch_bounds__(256) silu_guarded_kernel(
    const float4* __restrict__ in, float4* __restrict__ out, int n4)
{
    int base = blockIdx.x * 1024 + threadIdx.x;
    #pragma unroll
    for (int k = 0; k < 4; k++) {
        int i = base + k * 256;
        if (i < n4) __stcs(out + i, silu4(__ldcs(in + i)));
    }
}

// Tail for n not divisible by 4 (not hit for this shape).
__global__ void silu_tail_kernel(const float* __restrict__ in,
                                 float* __restrict__ out, int start, int n)
{
    int i = start + blockIdx.x * blockDim.x + threadIdx.x;
    if (i < n) out[i] = silu1(in[i]);
}

extern "C" void kernel_launch(void* const* d_in, const int* in_sizes, int n_in,
                              void* d_out, int out_size)
{
    const float* x = (const float*)d_in[0];
    float* y = (float*)d_out;
    int n = in_sizes[0];

    if (n > 0 && (n % 8192) == 0) {
        silu_v8_full_kernel<<<n / 8192, 512>>>(x, y);
        return;
    }

    int n4 = n / 4;
    if (n4 > 0) {
        if ((n4 & 2047) == 0) {
            silu_b512_full_kernel<<<n4 / 2048, 512>>>(
                (const float4*)x, (float4*)y);
        } else {
            silu_guarded_kernel<<<(n4 + 1023) / 1024, 256>>>(
                (const float4*)x, (float4*)y, n4);
        }
    }
    int rem = n - n4 * 4;
    if (rem > 0) {
        silu_tail_kernel<<<1, 256>>>(x, y, n4 * 4, n);
    }
}

// round 10
// speedup vs baseline: 1.0059x; 1.0059x over previous
#include <cuda_runtime.h>
#include <cuda_bf16.h>

// SiLU(x) = x * sigmoid(x), elementwise, n = 134217728 fp32.
// HBM-bound stream at the ~86% mixed R/W ceiling (~6.8 TB/s measured).
// R6-winner geometry (512 threads, 4 front-batched LDG.128/thread, .cs hints)
// + single-MUFU SiLU via tanh.approx: silu(x) = 0.5x*(1+tanh(x/2)).
// Halves MUFU issue traffic (EX2+RCP -> TANH) and shortens the dep chain.

__device__ __forceinline__ float silu1(float x) {
    float h = 0.5f * x;
    float t;
    asm("tanh.approx.f32 %0, %1;" : "=f"(t) : "f"(h));
    return fmaf(h, t, h);   // 0.5x*tanh(x/2) + 0.5x
}

__device__ __forceinline__ float4 silu4(float4 v) {
    float4 r;
    r.x = silu1(v.x);
    r.y = silu1(v.y);
    r.z = silu1(v.z);
    r.w = silu1(v.w);
    return r;
}

// Full-tile kernel: every block owns exactly 2048 float4s, no guards.
__global__ void __launch_bounds__(512) silu_b512_tanh_kernel(
    const float4* __restrict__ in, float4* __restrict__ out)
{
    unsigned base = blockIdx.x * 2048u + threadIdx.x;
    float4 v0 = __ldcs(in + base);
    float4 v1 = __ldcs(in + base + 512);
    float4 v2 = __ldcs(in + base + 1024);
    float4 v3 = __ldcs(in + base + 1536);
    __stcs(out + base,        silu4(v0));
    __stcs(out + base + 512,  silu4(v1));
    __stcs(out + base + 1024, silu4(v2));
    __stcs(out + base + 1536, silu4(v3));
}

// Generic guarded kernel (fallback for shapes not divisible by tile).
__global__ void __launch_bounds__(256) silu_guarded_kernel(
    const float4* __restrict__ in, float4* __restrict__ out, int n4)
{
    int base = blockIdx.x * 1024 + threadIdx.x;
    #pragma unroll
    for (int k = 0; k < 4; k++) {
        int i = base + k * 256;
        if (i < n4) __stcs(out + i, silu4(__ldcs(in + i)));
    }
}

// Tail for n not divisible by 4 (not hit for this shape).
__global__ void silu_tail_kernel(const float* __restrict__ in,
                                 float* __restrict__ out, int start, int n)
{
    int i = start + blockIdx.x * blockDim.x + threadIdx.x;
    if (i < n) out[i] = silu1(in[i]);
}

extern "C" void kernel_launch(void* const* d_in, const int* in_sizes, int n_in,
                              void* d_out, int out_size)
{
    const float* x = (const float*)d_in[0];
    float* y = (float*)d_out;
    int n = in_sizes[0];

    int n4 = n / 4;
    if (n4 > 0) {
        if ((n4 & 2047) == 0) {
            silu_b512_tanh_kernel<<<n4 / 2048, 512>>>(
                (const float4*)x, (float4*)y);
        } else {
            silu_guarded_kernel<<<(n4 + 1023) / 1024, 256>>>(
                (const float4*)x, (float4*)y, n4);
        }
    }
    int rem = n - n4 * 4;
    if (rem > 0) {
        silu_tail_kernel<<<1, 256>>>(x, y, n4 * 4, n);
    }
}